// round 11
// baseline (speedup 1.0000x reference)
#include <cuda_runtime.h>
#include <cuda_bf16.h>

#define M 512
#define NGRID 512          // CTA b handles row-line b AND col-line b
#define MARGIN 0.2f
#define NT 256             // threads per CTA
#define NB 256             // buckets == threads

__device__ float2 g_partials[2 * M];
__device__ int    g_count = 0;     // last-block ticket; reset by the finalizing block

__global__ __launch_bounds__(NT, 4)
void side_kernel(const float* __restrict__ scores,
                 const int* __restrict__ labels,
                 float* __restrict__ out) {
    // dual-stream state: index 0 = row-line, 1 = col-line
    __shared__ int   cnt[2][NB];
    __shared__ float fsum[2][NB];
    __shared__ int   off[2][NB];
    __shared__ int   cursor[2][NB];
    __shared__ float NVS[2][M];
    __shared__ float sufC[2][NB];
    __shared__ float sufS[2][NB];
    __shared__ int   wci[2][8];
    __shared__ float wcf[2][8];
    __shared__ float warp_sums[2][8];
    __shared__ bool  is_last;

    const int b    = blockIdx.x;
    const int t    = threadIdx.x;
    const int lane = t & 31;
    const int w    = t >> 5;

    // element indices: line 0 = row b (contiguous), line 1 = col b (strided)
    int idx[2][2];
    idx[0][0] = b * M + t;        idx[0][1] = idx[0][0] + NT;
    idx[1][0] = t * M + b;        idx[1][1] = idx[1][0] + NT * M;

    float s[2][2], x[2][2];
    bool  p[2][2];
    int   k[2][2];
    #pragma unroll
    for (int l = 0; l < 2; l++)
        #pragma unroll
        for (int e = 0; e < 2; e++) {
            s[l][e] = scores[idx[l][e]];
            p[l][e] = (labels[idx[l][e]] == 1);
            x[l][e] = p[l][e] ? s[l][e] : (s[l][e] + MARGIN);
            // monotone bucket: floor((x+8)*16) clamped to [0,255].
            // floor+clamp monotone => cross-bucket suffix exact;
            // same-bucket pairs handled by direct relu scan.
            k[l][e] = max(0, min(NB - 1, __float2int_rd((x[l][e] + 8.0f) * 16.0f)));
        }

    #pragma unroll
    for (int l = 0; l < 2; l++) { cnt[l][t] = 0; fsum[l][t] = 0.f; }
    __syncthreads();

    #pragma unroll
    for (int l = 0; l < 2; l++)
        #pragma unroll
        for (int e = 0; e < 2; e++)
            if (!p[l][e]) {
                atomicAdd(&cnt[l][k[l][e]], 1);
                atomicAdd(&fsum[l][k[l][e]], x[l][e]);
            }
    __syncthreads();

    // ---- block-wide inclusive scan over buckets, both lines interleaved ----
    int   c0[2], cc[2];
    float f0[2], ff[2];
    #pragma unroll
    for (int l = 0; l < 2; l++) {
        c0[l] = cnt[l][t];  cc[l] = c0[l];
        f0[l] = fsum[l][t]; ff[l] = f0[l];
    }
    #pragma unroll
    for (int o = 1; o < 32; o <<= 1) {
        #pragma unroll
        for (int l = 0; l < 2; l++) {
            int   nc = __shfl_up_sync(0xffffffffu, cc[l], o);
            float nf = __shfl_up_sync(0xffffffffu, ff[l], o);
            if (lane >= o) { cc[l] += nc; ff[l] += nf; }
        }
    }
    if (lane == 31)
        #pragma unroll
        for (int l = 0; l < 2; l++) { wci[l][w] = cc[l]; wcf[l][w] = ff[l]; }
    __syncthreads();

    if (t < 32) {
        int   ci[2]; float fi[2];
        #pragma unroll
        for (int l = 0; l < 2; l++) {
            ci[l] = (t < 8) ? wci[l][t] : 0;
            fi[l] = (t < 8) ? wcf[l][t] : 0.f;
        }
        #pragma unroll
        for (int o = 1; o < 8; o <<= 1) {
            #pragma unroll
            for (int l = 0; l < 2; l++) {
                int   nc = __shfl_up_sync(0xffffffffu, ci[l], o);
                float nf = __shfl_up_sync(0xffffffffu, fi[l], o);
                if (lane >= o) { ci[l] += nc; fi[l] += nf; }
            }
        }
        if (t < 8)
            #pragma unroll
            for (int l = 0; l < 2; l++) { wci[l][t] = ci[l]; wcf[l][t] = fi[l]; }
    }
    __syncthreads();

    int nn[2]; float totF[2];
    #pragma unroll
    for (int l = 0; l < 2; l++) {
        const int   incC = cc[l] + ((w > 0) ? wci[l][w - 1] : 0);
        const float incF = ff[l] + ((w > 0) ? wcf[l][w - 1] : 0.f);
        nn[l]   = wci[l][7];
        totF[l] = wcf[l][7];
        off[l][t]    = incC - c0[l];
        cursor[l][t] = incC - c0[l];
        sufC[l][t]   = (float)(nn[l] - incC);
        sufS[l][t]   = totF[l] - incF;
    }
    __syncthreads();

    // ---- counting scatter: group negs by bucket ----
    #pragma unroll
    for (int l = 0; l < 2; l++)
        #pragma unroll
        for (int e = 0; e < 2; e++)
            if (!p[l][e]) {
                int r = atomicAdd(&cursor[l][k[l][e]], 1);
                NVS[l][r] = x[l][e];
            }
    __syncthreads();

    // ---- per-pos evaluation: exact suffix part + same-bucket relu scan ----
    float tot[2] = {0.f, 0.f};
    #pragma unroll
    for (int l = 0; l < 2; l++)
        #pragma unroll
        for (int e = 0; e < 2; e++)
            if (p[l][e]) {
                const int   kk = k[l][e];
                const float ss = s[l][e];
                float a = fmaf(-sufC[l][kk], ss, sufS[l][kk]);
                const int j0 = off[l][kk], j1 = j0 + cnt[l][kk];
                for (int j = j0; j < j1; j++)
                    a += fmaxf(NVS[l][j] - ss, 0.f);
                tot[l] += a;
            }

    // ---- deterministic CTA reduction, both lines ----
    #pragma unroll
    for (int o = 16; o > 0; o >>= 1) {
        tot[0] += __shfl_down_sync(0xffffffffu, tot[0], o);
        tot[1] += __shfl_down_sync(0xffffffffu, tot[1], o);
    }
    if (lane == 0) { warp_sums[0][w] = tot[0]; warp_sums[1][w] = tot[1]; }
    __syncthreads();

    if (t < 32) {
        float v0 = (t < 8) ? warp_sums[0][t] : 0.f;
        float v1 = (t < 8) ? warp_sums[1][t] : 0.f;
        #pragma unroll
        for (int o = 4; o > 0; o >>= 1) {
            v0 += __shfl_down_sync(0xffffffffu, v0, o);
            v1 += __shfl_down_sync(0xffffffffu, v1, o);
        }
        if (t == 0) {
            #pragma unroll
            for (int l = 0; l < 2; l++) {
                const int   np    = M - nn[l];
                const bool  valid = (np > 0) && (nn[l] > 0);
                const float cntf  = (float)np * (float)nn[l];  // exact in fp32
                float2 pp;
                float  v = l ? v1 : v0;
                pp.x = valid ? (v / cntf) : 0.f;
                pp.y = valid ? 1.f : 0.f;
                g_partials[b + l * M] = pp;
            }
            __threadfence();
            int tk = atomicAdd(&g_count, 1);
            is_last = (tk == NGRID - 1);
        }
    }
    __syncthreads();

    // ---- last block: fixed-order global reduction + finalize ----
    if (is_last) {
        float m = 0.f, vv = 0.f;
        #pragma unroll
        for (int i = t; i < 2 * M; i += NT) {
            float2 pp = g_partials[i];
            m  += pp.x;
            vv += pp.y;
        }
        #pragma unroll
        for (int o = 16; o > 0; o >>= 1) {
            m  += __shfl_down_sync(0xffffffffu, m, o);
            vv += __shfl_down_sync(0xffffffffu, vv, o);
        }
        if (lane == 0) { warp_sums[0][w] = m; wcf[0][w] = vv; }
        __syncthreads();
        if (t < 32) {
            m  = (t < 8) ? warp_sums[0][t] : 0.f;
            vv = (t < 8) ? wcf[0][t] : 0.f;
            #pragma unroll
            for (int o = 4; o > 0; o >>= 1) {
                m  += __shfl_down_sync(0xffffffffu, m, o);
                vv += __shfl_down_sync(0xffffffffu, vv, o);
            }
            if (t == 0) {
                out[0] = m / vv;
                g_count = 0;                    // reset for next graph replay
            }
        }
    }
}

extern "C" void kernel_launch(void* const* d_in, const int* in_sizes, int n_in,
                              void* d_out, int out_size) {
    const float* scores = (const float*)d_in[0];
    const int*   labels = (const int*)d_in[1];
    float* out = (float*)d_out;

    side_kernel<<<NGRID, NT>>>(scores, labels, out);
}